// round 3
// baseline (speedup 1.0000x reference)
#include <cuda_runtime.h>

// SNN forward: T=1000, B=8192, I=9, H=96, O=3
// 16 lanes per batch (6 hidden units each), 2 batches per warp.
// State fusion: v = beta*mem1 - spk1. Layer-2 finalize deferred one step so
// the 16-lane shuffle-butterfly latency is off the critical path.

#define T_STEPS 1000
#define BATCHN  8192
#define BETA    0.92f

typedef unsigned long long u64;

static __device__ __forceinline__ u64 pk2(float lo, float hi) {
    u64 r; asm("mov.b64 %0,{%1,%2};" : "=l"(r) : "f"(lo), "f"(hi)); return r;
}
static __device__ __forceinline__ void upk2(u64 v, float& a, float& b) {
    asm("mov.b64 {%0,%1},%2;" : "=f"(a), "=f"(b) : "l"(v));
}
static __device__ __forceinline__ u64 ffma2(u64 a, u64 b, u64 c) {
    u64 d; asm("fma.rn.f32x2 %0,%1,%2,%3;" : "=l"(d) : "l"(a), "l"(b), "l"(c)); return d;
}
static __device__ __forceinline__ u64 fadd2(u64 a, u64 b) {
    u64 d; asm("add.rn.f32x2 %0,%1,%2;" : "=l"(d) : "l"(a), "l"(b)); return d;
}
static __device__ __forceinline__ u64 fmul2(u64 a, u64 b) {
    u64 d; asm("mul.rn.f32x2 %0,%1,%2;" : "=l"(d) : "l"(a), "l"(b)); return d;
}

__global__ void __launch_bounds__(64, 6) snn_kernel(
    const float* __restrict__ x,
    const float* __restrict__ W1,
    const float* __restrict__ b1,
    const float* __restrict__ W2,
    const float* __restrict__ b2,
    float* __restrict__ out)
{
    const int lane  = threadIdx.x & 31;
    const int gwarp = (blockIdx.x * 64 + threadIdx.x) >> 5;
    const int hl    = lane & 15;       // hidden slice index 0..15
    const int hb    = hl * 6;          // first hidden unit of this lane
    const int b     = gwarp * 2 + (lane >> 4);

    // ---- weights in registers, packed over hidden pairs ----
    u64 w1p[3][9];
    #pragma unroll
    for (int j = 0; j < 3; j++)
        #pragma unroll
        for (int i = 0; i < 9; i++)
            w1p[j][i] = pk2(W1[(hb + 2*j) * 9 + i], W1[(hb + 2*j + 1) * 9 + i]);

    u64 w2p[3][3];
    #pragma unroll
    for (int o = 0; o < 3; o++)
        #pragma unroll
        for (int j = 0; j < 3; j++)
            w2p[o][j] = pk2(W2[o * 96 + hb + 2*j], W2[o * 96 + hb + 2*j + 1]);

    u64 b1p[3];
    #pragma unroll
    for (int j = 0; j < 3; j++) b1p[j] = pk2(b1[hb + 2*j], b1[hb + 2*j + 1]);

    const float bb0 = b2[0], bb1 = b2[1], bb2v = b2[2];
    const u64 BET2 = pk2(BETA, BETA);

    // ---- state ----
    u64 v0 = 0ull, v1 = 0ull, v2 = 0ull;     // v = beta*mem1 - spk1
    float m2a = 0.f, m2b = 0.f, m2c = 0.f;   // mem2
    float ns0 = 0.f, ns1 = 0.f, ns2 = 0.f;   // -spk2 (previous)
    float p0 = 0.f, p1 = 0.f, p2 = 0.f;      // pending -sum(spk1*w2) of prev step

    const float* px = x + (size_t)b * 9;
    float* __restrict__ outs = out;
    float* __restrict__ outm = out + (size_t)T_STEPS * BATCHN * 3;

    float xa[9], xb[9];
    #pragma unroll
    for (int i = 0; i < 9; i++) xa[i] = __ldg(px + i);

    auto finalize = [&](int tprev) {
        float mm0 = fmaf(BETA, m2a, bb0 - p0) + ns0;
        float mm1 = fmaf(BETA, m2b, bb1 - p1) + ns1;
        float mm2 = fmaf(BETA, m2c, bb2v - p2) + ns2;
        m2a = mm0; m2b = mm1; m2c = mm2;
        ns0 = (mm0 > 1.0f) ? -1.0f : 0.0f;
        ns1 = (mm1 > 1.0f) ? -1.0f : 0.0f;
        ns2 = (mm2 > 1.0f) ? -1.0f : 0.0f;
        size_t ob = ((size_t)tprev * BATCHN + b) * 3;
        if (hl < 3) {
            float v = (hl == 0) ? -ns0 : ((hl == 1) ? -ns1 : -ns2);
            __stcs(outs + ob + hl, v);
        } else if (hl < 6) {
            float v = (hl == 3) ? mm0 : ((hl == 4) ? mm1 : mm2);
            __stcs(outm + ob + (hl - 3), v);
        }
    };

    auto step = [&](int t, float (&xcur)[9], float (&xnext)[9]) {
        // prefetch next x (a full step of latency distance)
        const float* pn = px + (size_t)((t + 1 < T_STEPS) ? (t + 1) : t) * (BATCHN * 9);
        #pragma unroll
        for (int i = 0; i < 9; i++) xnext[i] = __ldg(pn + i);

        // layer 1: mem1 = x@W1^T + b1 + v
        u64 a0 = b1p[0], a1 = b1p[1], a2 = b1p[2];
        #pragma unroll
        for (int i = 0; i < 9; i++) {
            u64 xp = pk2(xcur[i], xcur[i]);
            a0 = ffma2(w1p[0][i], xp, a0);
            a1 = ffma2(w1p[1][i], xp, a1);
            a2 = ffma2(w1p[2][i], xp, a2);
        }
        a0 = fadd2(a0, v0); a1 = fadd2(a1, v1); a2 = fadd2(a2, v2);

        // spikes (negated) + fused state update v = beta*mem1 - spk
        float f0, f1;
        upk2(a0, f0, f1);
        u64 q0 = pk2((f0 > 1.0f) ? -1.0f : 0.0f, (f1 > 1.0f) ? -1.0f : 0.0f);
        upk2(a1, f0, f1);
        u64 q1 = pk2((f0 > 1.0f) ? -1.0f : 0.0f, (f1 > 1.0f) ? -1.0f : 0.0f);
        upk2(a2, f0, f1);
        u64 q2 = pk2((f0 > 1.0f) ? -1.0f : 0.0f, (f1 > 1.0f) ? -1.0f : 0.0f);
        v0 = ffma2(BET2, a0, q0);
        v1 = ffma2(BET2, a1, q1);
        v2 = ffma2(BET2, a2, q2);

        // layer-2 partials (accumulate -spk*w2)
        u64 c0 = fmul2(q0, w2p[0][0]); c0 = ffma2(q1, w2p[0][1], c0); c0 = ffma2(q2, w2p[0][2], c0);
        u64 c1 = fmul2(q0, w2p[1][0]); c1 = ffma2(q1, w2p[1][1], c1); c1 = ffma2(q2, w2p[1][2], c1);
        u64 c2 = fmul2(q0, w2p[2][0]); c2 = ffma2(q1, w2p[2][1], c2); c2 = ffma2(q2, w2p[2][2], c2);
        float s0, s1, s2, ta, tb;
        upk2(c0, ta, tb); s0 = ta + tb;
        upk2(c1, ta, tb); s1 = ta + tb;
        upk2(c2, ta, tb); s2 = ta + tb;

        // 16-lane butterfly reduce (xor distances stay within each 16-lane group)
        #pragma unroll
        for (int d = 8; d >= 1; d >>= 1) {
            s0 += __shfl_xor_sync(0xffffffffu, s0, d);
            s1 += __shfl_xor_sync(0xffffffffu, s1, d);
            s2 += __shfl_xor_sync(0xffffffffu, s2, d);
        }

        // finalize the PREVIOUS step while this step's shuffles drain
        if (t) finalize(t - 1);
        p0 = s0; p1 = s1; p2 = s2;
    };

    for (int t = 0; t < T_STEPS; t += 2) {
        step(t,     xa, xb);
        step(t + 1, xb, xa);
    }
    finalize(T_STEPS - 1);
}

extern "C" void kernel_launch(void* const* d_in, const int* in_sizes, int n_in,
                              void* d_out, int out_size) {
    const float* x  = (const float*)d_in[0];
    const float* W1 = (const float*)d_in[1];
    const float* b1 = (const float*)d_in[2];
    const float* W2 = (const float*)d_in[3];
    const float* b2 = (const float*)d_in[4];
    float* out = (float*)d_out;

    // 8192 batches * 16 lanes = 131072 threads; 64 threads/CTA -> 2048 CTAs
    snn_kernel<<<2048, 64>>>(x, W1, b1, W2, b2, out);
}

// round 5
// speedup vs baseline: 1.5806x; 1.5806x over previous
#include <cuda_runtime.h>

// SNN forward: T=1000, B=8192, I=9, H=96, O=3
// 16 lanes/batch (6 h each), 2 batches/warp, 4 warps/CTA, <=128 regs (4 w/SMSP).
// v = beta*mem1 - spk1 state fusion; layer-2 finalize deferred one step.
// Two-phase butterfly reduction; one output per finalize lane.
// x staged through a warp-private 3-deep smem ring as duplicated f32 pairs.

#define T_STEPS 1000
#define BATCHN  8192
#define BETA    0.92f

typedef unsigned long long u64;

static __device__ __forceinline__ u64 pk2(float lo, float hi) {
    u64 r; asm("mov.b64 %0,{%1,%2};" : "=l"(r) : "f"(lo), "f"(hi)); return r;
}
static __device__ __forceinline__ void upk2(u64 v, float& a, float& b) {
    asm("mov.b64 {%0,%1},%2;" : "=f"(a), "=f"(b) : "l"(v));
}
static __device__ __forceinline__ u64 ffma2(u64 a, u64 b, u64 c) {
    u64 d; asm("fma.rn.f32x2 %0,%1,%2,%3;" : "=l"(d) : "l"(a), "l"(b), "l"(c)); return d;
}
static __device__ __forceinline__ u64 fadd2(u64 a, u64 b) {
    u64 d; asm("add.rn.f32x2 %0,%1,%2;" : "=l"(d) : "l"(a), "l"(b)); return d;
}
static __device__ __forceinline__ u64 fmul2(u64 a, u64 b) {
    u64 d; asm("mul.rn.f32x2 %0,%1,%2;" : "=l"(d) : "l"(a), "l"(b)); return d;
}

__global__ void __launch_bounds__(128, 4) snn_kernel(
    const float* __restrict__ x,
    const float* __restrict__ W1,
    const float* __restrict__ b1,
    const float* __restrict__ W2,
    const float* __restrict__ b2,
    float* __restrict__ out)
{
    const int lane = threadIdx.x & 31;
    const int warp = threadIdx.x >> 5;
    const int gw   = blockIdx.x * 4 + warp;      // global warp
    const int grp  = lane >> 4;                  // batch slot within warp
    const int hl   = lane & 15;                  // hidden slice 0..15
    const int hb   = hl * 6;
    const int b    = gw * 2 + grp;

    // x staging ring: [warp][buf3][batchslot][i], duplicated f32 pairs
    __shared__ u64 xs[4][3][2][9];

    // ---- weights in registers ----
    u64 w1p[3][9];
    #pragma unroll
    for (int j = 0; j < 3; j++)
        #pragma unroll
        for (int i = 0; i < 9; i++)
            w1p[j][i] = pk2(W1[(hb + 2*j) * 9 + i], W1[(hb + 2*j + 1) * 9 + i]);

    u64 w2p[3][3];
    #pragma unroll
    for (int o = 0; o < 3; o++)
        #pragma unroll
        for (int j = 0; j < 3; j++)
            w2p[o][j] = pk2(W2[o * 96 + hb + 2*j], W2[o * 96 + hb + 2*j + 1]);

    const u64* __restrict__ b1q = (const u64*)b1;   // b1 pairs, L1-resident
    const u64 BET2 = pk2(BETA, BETA);

    // ---- finalize lane roles: output o = hl>>2, role hl&3: 0=spk,1=mem ----
    const int  oc        = (hl >> 2) > 2 ? 2 : (hl >> 2);
    const bool fin_store = ((hl & 3) < 2) && (hl < 12);
    const bool is_spk    = (hl & 3) == 0;
    const float bias     = b2[oc];

    float* optr = (is_spk ? out : out + (size_t)T_STEPS * BATCHN * 3)
                  + (size_t)b * 3 + oc;           // slot 0; bumped only on stores

    // ---- state ----
    u64 v0 = 0ull, v1 = 0ull, v2 = 0ull;   // v = beta*mem1 - spk1
    float m2 = 0.f, ns = 0.f;
    float p  = bias;                        // t=0 finalize computes mm = 0

    // ---- x loader pipeline (lanes 0..17 load 2 batches x 9 inputs) ----
    const bool loader = lane < 18;
    const int  gl = lane / 9, il = lane - gl * 9;
    const float* xb = x + (size_t)(gw * 2 + gl) * 9 + il;
    const size_t xstr = (size_t)BATCHN * 9;

    float r0 = loader ? xb[0] : 0.f;
    if (loader) xs[warp][0][gl][il] = pk2(r0, r0);          // buf0 = x(0)
    float r = loader ? xb[xstr] : 0.f;                      // in flight: x(1)
    __syncwarp();

    int bcur = 0, bnext = 1, bnn = 2;
    #pragma unroll 3
    for (int t = 0; t < T_STEPS; t++) {
        // stage x(t+1) into bnext, launch load of x(t+2)
        if (loader) xs[warp][bnext][gl][il] = pk2(r, r);
        {
            int tn = (t + 2 < T_STEPS) ? (t + 2) : (T_STEPS - 1);
            r = loader ? xb[(size_t)tn * xstr] : 0.f;
        }
        __syncwarp();

        // ---- layer 1: mem1 = x@W1^T + b1 + v ----
        u64 a0 = b1q[hl * 3 + 0];
        u64 a1 = b1q[hl * 3 + 1];
        u64 a2 = b1q[hl * 3 + 2];
        #pragma unroll
        for (int i = 0; i < 9; i++) {
            u64 xp = xs[warp][bcur][grp][i];
            a0 = ffma2(w1p[0][i], xp, a0);
            a1 = ffma2(w1p[1][i], xp, a1);
            a2 = ffma2(w1p[2][i], xp, a2);
        }
        a0 = fadd2(a0, v0); a1 = fadd2(a1, v1); a2 = fadd2(a2, v2);

        // ---- spikes (negated) + state v = beta*mem1 - spk ----
        float f0, f1;
        upk2(a0, f0, f1);
        u64 q0 = pk2((f0 > 1.0f) ? -1.0f : 0.0f, (f1 > 1.0f) ? -1.0f : 0.0f);
        upk2(a1, f0, f1);
        u64 q1 = pk2((f0 > 1.0f) ? -1.0f : 0.0f, (f1 > 1.0f) ? -1.0f : 0.0f);
        upk2(a2, f0, f1);
        u64 q2 = pk2((f0 > 1.0f) ? -1.0f : 0.0f, (f1 > 1.0f) ? -1.0f : 0.0f);
        v0 = ffma2(BET2, a0, q0);
        v1 = ffma2(BET2, a1, q1);
        v2 = ffma2(BET2, a2, q2);

        // ---- layer-2 partials: c_o = sum(-spk * w2[o]) ----
        u64 c0 = fmul2(q0, w2p[0][0]); c0 = ffma2(q1, w2p[0][1], c0); c0 = ffma2(q2, w2p[0][2], c0);
        u64 c1 = fmul2(q0, w2p[1][0]); c1 = ffma2(q1, w2p[1][1], c1); c1 = ffma2(q2, w2p[1][2], c1);
        u64 c2 = fmul2(q0, w2p[2][0]); c2 = ffma2(q1, w2p[2][1], c2); c2 = ffma2(q2, w2p[2][2], c2);
        float s0, s1, s2, ta, tb;
        upk2(c0, ta, tb); s0 = ta + tb;
        upk2(c1, ta, tb); s1 = ta + tb;
        upk2(c2, ta, tb); s2 = ta + tb;

        // ---- two-phase reduction over the 16-lane group ----
        s0 += __shfl_xor_sync(0xffffffffu, s0, 8);
        s1 += __shfl_xor_sync(0xffffffffu, s1, 8);
        s2 += __shfl_xor_sync(0xffffffffu, s2, 8);
        s0 += __shfl_xor_sync(0xffffffffu, s0, 4);
        s1 += __shfl_xor_sync(0xffffffffu, s1, 4);
        s2 += __shfl_xor_sync(0xffffffffu, s2, 4);
        float sv = (oc == 0) ? s0 : ((oc == 1) ? s1 : s2);
        sv += __shfl_xor_sync(0xffffffffu, sv, 2);
        sv += __shfl_xor_sync(0xffffffffu, sv, 1);

        // ---- finalize previous step (this step's shuffles drain meanwhile) ----
        {
            float mm = fmaf(BETA, m2, bias - p) + ns;
            m2 = mm;
            float spkv = (mm > 1.0f) ? 1.0f : 0.0f;
            ns = (mm > 1.0f) ? -1.0f : 0.0f;
            if (t) {                          // iteration t finalizes timestep t-1
                if (fin_store) __stcs(optr, is_spk ? spkv : mm);
                optr += 3 * BATCHN;           // bump ONLY when a slot was consumed
            }
        }
        p = sv;

        int tmp = bcur; bcur = bnext; bnext = bnn; bnn = tmp;
    }

    // final timestep T-1 (optr now at slot T-1)
    {
        float mm = fmaf(BETA, m2, bias - p) + ns;
        if (fin_store) {
            float spkv = (mm > 1.0f) ? 1.0f : 0.0f;
            __stcs(optr, is_spk ? spkv : mm);
        }
    }
}

extern "C" void kernel_launch(void* const* d_in, const int* in_sizes, int n_in,
                              void* d_out, int out_size) {
    const float* x  = (const float*)d_in[0];
    const float* W1 = (const float*)d_in[1];
    const float* b1 = (const float*)d_in[2];
    const float* W2 = (const float*)d_in[3];
    const float* b2 = (const float*)d_in[4];
    float* out = (float*)d_out;

    // 8192 batches / (2 per warp * 4 warps) = 1024 CTAs
    snn_kernel<<<1024, 128>>>(x, W1, b1, W2, b2, out);
}

// round 6
// speedup vs baseline: 1.5917x; 1.0070x over previous
#include <cuda_runtime.h>

// SNN forward: T=1000, B=8192, I=9, H=96, O=3
// 16 lanes/batch (6 h each), 2 batches/warp, 4 warps/CTA, 4 CTAs/SM.
// State fusion v = beta*mem1 + b1 - spk1  (b1 folded: no per-step bias load,
// layer-1 accumulator starts directly from the v register).
// Layer-2 finalize deferred one step; two-phase butterfly reduction.
// x staged through a warp-private 3-deep smem ring, read with LDS.128.

#define T_STEPS 1000
#define BATCHN  8192
#define BETA    0.92f

typedef unsigned long long u64;

static __device__ __forceinline__ u64 pk2(float lo, float hi) {
    u64 r; asm("mov.b64 %0,{%1,%2};" : "=l"(r) : "f"(lo), "f"(hi)); return r;
}
static __device__ __forceinline__ void upk2(u64 v, float& a, float& b) {
    asm("mov.b64 {%0,%1},%2;" : "=f"(a), "=f"(b) : "l"(v));
}
static __device__ __forceinline__ u64 ffma2(u64 a, u64 b, u64 c) {
    u64 d; asm("fma.rn.f32x2 %0,%1,%2,%3;" : "=l"(d) : "l"(a), "l"(b), "l"(c)); return d;
}
static __device__ __forceinline__ u64 fadd2(u64 a, u64 b) {
    u64 d; asm("add.rn.f32x2 %0,%1,%2;" : "=l"(d) : "l"(a), "l"(b)); return d;
}
static __device__ __forceinline__ u64 fmul2(u64 a, u64 b) {
    u64 d; asm("mul.rn.f32x2 %0,%1,%2;" : "=l"(d) : "l"(a), "l"(b)); return d;
}
static __device__ __forceinline__ void lds128(u64& a, u64& b, const u64* p) {
    asm("ld.shared.v2.u64 {%0,%1},[%2];" : "=l"(a), "=l"(b) : "l"(__cvta_generic_to_shared(p)));
}

__global__ void __launch_bounds__(128, 4) snn_kernel(
    const float* __restrict__ x,
    const float* __restrict__ W1,
    const float* __restrict__ b1,
    const float* __restrict__ W2,
    const float* __restrict__ b2,
    float* __restrict__ out)
{
    const int lane = threadIdx.x & 31;
    const int warp = threadIdx.x >> 5;
    const int gw   = blockIdx.x * 4 + warp;
    const int grp  = lane >> 4;                  // batch slot within warp
    const int hl   = lane & 15;                  // hidden slice 0..15
    const int hb   = hl * 6;
    const int b    = gw * 2 + grp;

    // x staging ring: [warp][buf3][batchslot][10] (padded to 80B => 16B aligned rows)
    __shared__ __align__(16) u64 xs[4][3][2][10];

    // ---- weights in registers ----
    u64 w1p[3][9];
    #pragma unroll
    for (int j = 0; j < 3; j++)
        #pragma unroll
        for (int i = 0; i < 9; i++)
            w1p[j][i] = pk2(W1[(hb + 2*j) * 9 + i], W1[(hb + 2*j + 1) * 9 + i]);

    u64 w2p[3][3];
    #pragma unroll
    for (int o = 0; o < 3; o++)
        #pragma unroll
        for (int j = 0; j < 3; j++)
            w2p[o][j] = pk2(W2[o * 96 + hb + 2*j], W2[o * 96 + hb + 2*j + 1]);

    u64 b1p[3];
    #pragma unroll
    for (int j = 0; j < 3; j++) b1p[j] = pk2(b1[hb + 2*j], b1[hb + 2*j + 1]);

    const u64 BET2 = pk2(BETA, BETA);

    // ---- finalize lane roles: output o = hl>>2 (capped), role hl&3: 0=spk,1=mem ----
    const int  oc        = (hl >> 2) > 2 ? 2 : (hl >> 2);
    const bool fin_store = ((hl & 3) < 2) && (hl < 12);
    const bool is_spk    = (hl & 3) == 0;
    const float bias     = b2[oc];

    float* optr = (is_spk ? out : out + (size_t)T_STEPS * BATCHN * 3)
                  + (size_t)b * 3 + oc;

    // ---- state:  v = beta*mem1 + b1 - spk1  (init: b1) ----
    u64 v0 = b1p[0], v1 = b1p[1], v2 = b1p[2];
    float m2 = 0.f, ns = 0.f;
    float p  = bias;                        // t=0 finalize computes mm = 0

    // ---- x loader pipeline (lanes 0..17 load 2 batches x 9 inputs) ----
    const bool loader = lane < 18;
    const int  gl = lane / 9, il = lane - gl * 9;
    const float* xb = x + (size_t)(gw * 2 + gl) * 9 + il;
    const size_t xstr = (size_t)BATCHN * 9;

    float r = loader ? xb[0] : 0.f;
    if (loader) xs[warp][0][gl][il] = pk2(r, r);            // buf0 = x(0)
    r = loader ? xb[xstr] : 0.f;                            // in flight: x(1)
    __syncwarp();

    int bcur = 0, bnext = 1, bnn = 2;
    #pragma unroll 3
    for (int t = 0; t < T_STEPS; t++) {
        // stage x(t+1) into bnext, launch load of x(t+2)
        if (loader) xs[warp][bnext][gl][il] = pk2(r, r);
        {
            int tn = (t + 2 < T_STEPS) ? (t + 2) : (T_STEPS - 1);
            r = loader ? xb[(size_t)tn * xstr] : 0.f;
        }
        __syncwarp();

        // ---- load x pairs: 4x LDS.128 + 1x LDS.64 ----
        const u64* xrow = xs[warp][bcur][grp];
        u64 xp[9];
        lds128(xp[0], xp[1], xrow + 0);
        lds128(xp[2], xp[3], xrow + 2);
        lds128(xp[4], xp[5], xrow + 4);
        lds128(xp[6], xp[7], xrow + 6);
        xp[8] = xrow[8];

        // ---- layer 1: a = v + x@W1^T   (v already holds beta*mem1 + b1 - spk) ----
        u64 a0 = v0, a1 = v1, a2 = v2;
        #pragma unroll
        for (int i = 0; i < 9; i++) {
            a0 = ffma2(w1p[0][i], xp[i], a0);
            a1 = ffma2(w1p[1][i], xp[i], a1);
            a2 = ffma2(w1p[2][i], xp[i], a2);
        }

        // ---- spikes (negated) + state v = beta*a + (q + b1) ----
        float f0, f1;
        upk2(a0, f0, f1);
        u64 q0 = pk2((f0 > 1.0f) ? -1.0f : 0.0f, (f1 > 1.0f) ? -1.0f : 0.0f);
        upk2(a1, f0, f1);
        u64 q1 = pk2((f0 > 1.0f) ? -1.0f : 0.0f, (f1 > 1.0f) ? -1.0f : 0.0f);
        upk2(a2, f0, f1);
        u64 q2 = pk2((f0 > 1.0f) ? -1.0f : 0.0f, (f1 > 1.0f) ? -1.0f : 0.0f);
        v0 = ffma2(BET2, a0, fadd2(q0, b1p[0]));
        v1 = ffma2(BET2, a1, fadd2(q1, b1p[1]));
        v2 = ffma2(BET2, a2, fadd2(q2, b1p[2]));

        // ---- layer-2 partials: c_o = sum(-spk * w2[o]) ----
        u64 c0 = fmul2(q0, w2p[0][0]); c0 = ffma2(q1, w2p[0][1], c0); c0 = ffma2(q2, w2p[0][2], c0);
        u64 c1 = fmul2(q0, w2p[1][0]); c1 = ffma2(q1, w2p[1][1], c1); c1 = ffma2(q2, w2p[1][2], c1);
        u64 c2 = fmul2(q0, w2p[2][0]); c2 = ffma2(q1, w2p[2][1], c2); c2 = ffma2(q2, w2p[2][2], c2);
        float s0, s1, s2, ta, tb;
        upk2(c0, ta, tb); s0 = ta + tb;
        upk2(c1, ta, tb); s1 = ta + tb;
        upk2(c2, ta, tb); s2 = ta + tb;

        // ---- two-phase reduction over the 16-lane group ----
        s0 += __shfl_xor_sync(0xffffffffu, s0, 8);
        s1 += __shfl_xor_sync(0xffffffffu, s1, 8);
        s2 += __shfl_xor_sync(0xffffffffu, s2, 8);
        s0 += __shfl_xor_sync(0xffffffffu, s0, 4);
        s1 += __shfl_xor_sync(0xffffffffu, s1, 4);
        s2 += __shfl_xor_sync(0xffffffffu, s2, 4);
        float sv = (oc == 0) ? s0 : ((oc == 1) ? s1 : s2);
        sv += __shfl_xor_sync(0xffffffffu, sv, 2);
        sv += __shfl_xor_sync(0xffffffffu, sv, 1);

        // ---- finalize previous step (this step's shuffles drain meanwhile) ----
        {
            float mm = fmaf(BETA, m2, bias - p) + ns;
            m2 = mm;
            float spkv = (mm > 1.0f) ? 1.0f : 0.0f;
            ns = (mm > 1.0f) ? -1.0f : 0.0f;
            if (t) {                          // iteration t finalizes timestep t-1
                if (fin_store) __stcs(optr, is_spk ? spkv : mm);
                optr += 3 * BATCHN;
            }
        }
        p = sv;

        int tmp = bcur; bcur = bnext; bnext = bnn; bnn = tmp;
    }

    // final timestep T-1
    {
        float mm = fmaf(BETA, m2, bias - p) + ns;
        if (fin_store) {
            float spkv = (mm > 1.0f) ? 1.0f : 0.0f;
            __stcs(optr, is_spk ? spkv : mm);
        }
    }
}

extern "C" void kernel_launch(void* const* d_in, const int* in_sizes, int n_in,
                              void* d_out, int out_size) {
    const float* x  = (const float*)d_in[0];
    const float* W1 = (const float*)d_in[1];
    const float* b1 = (const float*)d_in[2];
    const float* W2 = (const float*)d_in[3];
    const float* b2 = (const float*)d_in[4];
    float* out = (float*)d_out;

    snn_kernel<<<1024, 128>>>(x, W1, b1, W2, b2, out);
}